// round 17
// baseline (speedup 1.0000x reference)
#include <cuda_runtime.h>
#include <cuda_fp16.h>
#include <cstdint>

// Problem constants: qkv (B,S,3,H,D) fp32
#define B_   2
#define S_   2048
#define H_   16
#define D_   64
#define BH_  32

#define U_SCALE   0.0625f
#define U_UNSCALE 16.0f

__device__ uint32_t g_k[(size_t)BH_ * S_ * 32];
__device__ uint32_t g_v[(size_t)BH_ * S_ * 32];

__device__ __forceinline__ uint32_t smem_u32(const void* p) {
    uint32_t a;
    asm("{ .reg .u64 t; cvta.to.shared.u64 t, %1; cvt.u32.u64 %0, t; }" : "=r"(a) : "l"(p));
    return a;
}
__device__ __forceinline__ uint32_t sw128(uint32_t off) { return off ^ ((off >> 3) & 0x70); }

__device__ __forceinline__ uint32_t pack_f16(float x0, float x1) {
    uint32_t r;
    asm("cvt.rn.f16x2.f32 %0, %1, %2;" : "=r"(r) : "f"(x1), "f"(x0));
    return r;
}

// ---------------------------------------------------------------------------
// ldmatrix / mma (fragment mappings validated rounds 3-16)
// ---------------------------------------------------------------------------
__device__ __forceinline__ void ldsm_x4(uint32_t base, int r_base, int c_base, int lane, uint32_t r[4]) {
    uint32_t off = (uint32_t)((r_base + (lane & 15)) * 128 + (c_base + ((lane >> 4) << 3)) * 2);
    uint32_t addr = base + sw128(off);
    asm volatile("ldmatrix.sync.aligned.m8n8.x4.shared.b16 {%0,%1,%2,%3}, [%4];"
                 : "=r"(r[0]), "=r"(r[1]), "=r"(r[2]), "=r"(r[3]) : "r"(addr));
}
__device__ __forceinline__ void ldsm_x4_t(uint32_t base, int r_base, int c_base, int lane, uint32_t r[4]) {
    uint32_t off = (uint32_t)((r_base + (lane & 15)) * 128 + (c_base + ((lane >> 4) << 3)) * 2);
    uint32_t addr = base + sw128(off);
    asm volatile("ldmatrix.sync.aligned.m8n8.x4.trans.shared.b16 {%0,%1,%2,%3}, [%4];"
                 : "=r"(r[0]), "=r"(r[1]), "=r"(r[2]), "=r"(r[3]) : "r"(addr));
}
__device__ __forceinline__ void mma16816(float c[4], const uint32_t a[4], const uint32_t b[2]) {
    asm volatile("mma.sync.aligned.m16n8k16.row.col.f32.f16.f16.f32 "
                 "{%0,%1,%2,%3}, {%4,%5,%6,%7}, {%8,%9}, {%0,%1,%2,%3};"
                 : "+f"(c[0]), "+f"(c[1]), "+f"(c[2]), "+f"(c[3])
                 : "r"(a[0]), "r"(a[1]), "r"(a[2]), "r"(a[3]), "r"(b[0]), "r"(b[1]));
}

// B-frags, trans ([k][n]), n=64 (stage 2)
__device__ __forceinline__ void load_b_t1(uint32_t base, int kk, int lane, uint32_t bf[8][2]) {
#pragma unroll
    for (int nq = 0; nq < 4; nq++) {
        uint32_t r[4];
        ldsm_x4_t(base, kk, nq * 16, lane, r);
        bf[2*nq][0] = r[0]; bf[2*nq][1] = r[1]; bf[2*nq+1][0] = r[2]; bf[2*nq+1][1] = r[3];
    }
}

// mask a half (4 nf frags starting at nfbase) of one m16 subtile
__device__ __forceinline__ void mask_half(float (&s1)[8][4], int nfbase, int colbase,
                                          int t0mi, int cp0) {
#pragma unroll
    for (int nf = 0; nf < 4; nf++)
#pragma unroll
        for (int e = 0; e < 4; e++) {
            int srow = t0mi + ((e >> 1) << 3);
            int scol = colbase + (nfbase + nf) * 8 + cp0 + (e & 1);
            if (scol > srow) s1[nfbase + nf][e] = 0.0f;
        }
}
// conv a half: s1[2kf],s1[2kf+1] -> af[kf], for kf in {kfbase, kfbase+1}
__device__ __forceinline__ void conv_half(const float (&s1)[8][4], uint32_t (&af)[4][4], int kfbase) {
#pragma unroll
    for (int kf = kfbase; kf < kfbase + 2; kf++) {
        af[kf][0] = pack_f16(s1[2*kf  ][0], s1[2*kf  ][1]);
        af[kf][1] = pack_f16(s1[2*kf  ][2], s1[2*kf  ][3]);
        af[kf][2] = pack_f16(s1[2*kf+1][0], s1[2*kf+1][1]);
        af[kf][3] = pack_f16(s1[2*kf+1][2], s1[2*kf+1][3]);
    }
}

// ---------------------------------------------------------------------------
// One 64-col chunk for an m32 warp tile (R12/R16-proven body + half-skip).
// skip_hi: the chunk's upper 32 columns are entirely above this warp's rows --
// their post-mask `a` values are exactly zero, so all their stage-1 and
// stage-2 work can be dropped with a bit-identical result.
// ---------------------------------------------------------------------------
__device__ __forceinline__ void chunk_gemm(uint32_t kb, uint32_t s2b,
                                           const uint32_t (&aF)[2][4][4], float (&acc)[2][8][4],
                                           int lane, int t0, int cp0, int colbase, bool diag,
                                           bool skip_hi) {
    float s1[2][8][4] = {};
#pragma unroll
    for (int kd = 0; kd < 4; kd++) {
        uint32_t r0[4], r1[4];
        ldsm_x4(kb, 0,  kd * 16, lane, r0);
        ldsm_x4(kb, 16, kd * 16, lane, r1);
        uint32_t bf[4][2];
        bf[0][0] = r0[0]; bf[0][1] = r0[2]; bf[1][0] = r0[1]; bf[1][1] = r0[3];
        bf[2][0] = r1[0]; bf[2][1] = r1[2]; bf[3][0] = r1[1]; bf[3][1] = r1[3];
#pragma unroll
        for (int mi = 0; mi < 2; mi++)
#pragma unroll
            for (int nf = 0; nf < 4; nf++) mma16816(s1[mi][nf], aF[mi][kd], bf[nf]);
    }
    if (!skip_hi) {
#pragma unroll
        for (int kd = 0; kd < 4; kd++) {
            uint32_t r0[4], r1[4];
            ldsm_x4(kb, 32, kd * 16, lane, r0);
            ldsm_x4(kb, 48, kd * 16, lane, r1);
            uint32_t bf[4][2];
            bf[0][0] = r0[0]; bf[0][1] = r0[2]; bf[1][0] = r0[1]; bf[1][1] = r0[3];
            bf[2][0] = r1[0]; bf[2][1] = r1[2]; bf[3][0] = r1[1]; bf[3][1] = r1[3];
#pragma unroll
            for (int mi = 0; mi < 2; mi++)
#pragma unroll
                for (int nf = 0; nf < 4; nf++) mma16816(s1[mi][4 + nf], aF[mi][kd], bf[nf]);
        }
    }
    uint32_t af[2][4][4];
#pragma unroll
    for (int mi = 0; mi < 2; mi++) {
        if (diag) mask_half(s1[mi], 0, colbase, t0 + mi * 16, cp0);
        conv_half(s1[mi], af[mi], 0);
    }
#pragma unroll
    for (int ks = 0; ks < 2; ks++) {
        uint32_t bf[8][2];
        load_b_t1(s2b, ks * 16, lane, bf);
#pragma unroll
        for (int mi = 0; mi < 2; mi++)
#pragma unroll
            for (int nf = 0; nf < 8; nf++) mma16816(acc[mi][nf], af[mi][ks], bf[nf]);
    }
    if (!skip_hi) {
#pragma unroll
        for (int mi = 0; mi < 2; mi++) {
            if (diag) mask_half(s1[mi], 4, colbase, t0 + mi * 16, cp0);
            conv_half(s1[mi], af[mi], 2);
        }
#pragma unroll
        for (int ks = 2; ks < 4; ks++) {
            uint32_t bf[8][2];
            load_b_t1(s2b, ks * 16, lane, bf);
#pragma unroll
            for (int mi = 0; mi < 2; mi++)
#pragma unroll
                for (int nf = 0; nf < 8; nf++) mma16816(acc[mi][nf], af[mi][ks], bf[nf]);
        }
    }
}

// ---------------------------------------------------------------------------
// cp.async: single 64-row x 128B panel, SW128 swizzled (128 threads)
// ---------------------------------------------------------------------------
__device__ __forceinline__ void cpa16(uint32_t smaddr, const void* gaddr) {
    asm volatile("cp.async.cg.shared.global [%0], [%1], 16;" :: "r"(smaddr), "l"(gaddr));
}
__device__ __forceinline__ void issue_panel1(const uint32_t* g, uint32_t sm, int tid) {
    for (int i = tid; i < 512; i += 128) {
        int r = i >> 3, c = i & 7;
        uint32_t off = sw128((uint32_t)(r * 128 + c * 16));
        cpa16(sm + off, g + r * 32 + c * 4);
    }
}
#define CP_COMMIT() asm volatile("cp.async.commit_group;" ::: "memory")
#define CP_WAIT1()  asm volatile("cp.async.wait_group 1;" ::: "memory")
#define CP_WAIT0()  asm volatile("cp.async.wait_group 0;" ::: "memory")

// ===========================================================================
// Preprocess: k/v only -> fp16, head-major rows of 64. float4-vectorized.
// ===========================================================================
__global__ __launch_bounds__(256) void prep(const float* __restrict__ qkv) {
    int idx = blockIdx.x * 256 + threadIdx.x;       // B*S*2*H*16 threads
    int c4 = idx & 15;
    int h  = (idx >> 4) & 15;
    int w2 = (idx >> 8) & 1;                        // 0 = k, 1 = v
    int sb = idx >> 9;
    int s  = sb & (S_ - 1);
    int b  = sb >> 11;
    const float* src = qkv + ((size_t)(b * S_ + s) * 3 + (w2 + 1)) * (H_ * D_) + h * D_ + c4 * 4;
    float4 v = *reinterpret_cast<const float4*>(src);
    uint32_t p0 = pack_f16(v.x, v.y);
    uint32_t p1 = pack_f16(v.z, v.w);
    size_t dst = ((size_t)(b * 16 + h) * S_ + s) * 32 + c4 * 2;
    uint32_t* g = w2 ? g_v : g_k;
    g[dst] = p0; g[dst + 1] = p1;
}

// smem: V ring [0,24K) (q staging [0,16K) aliases V0/V1, dead before phase 2)
//       K ring [24K,48K)
#define SMQ 0
#define SMV(st) ((st) * 8192)
#define SMK(st) (24576 + (st) * 8192)
#define SMEM_BYTES 49152

// ===========================================================================
// Fused, 128 threads / 4 warps, m32 warp tiles (R16 structure + half-skip).
// phase 1: o2 = tril(q kT) k, u = (2q-o2)/16 in REGISTERS
// phase 2: out = tril(u kT) v * 16
// ===========================================================================
__global__ __launch_bounds__(128, 2) void fused(const float* __restrict__ qkv,
                                                float* __restrict__ out) {
    int bh = blockIdx.y, tt = 15 - (int)blockIdx.x;
    extern __shared__ __align__(1024) char smem[];
    uint32_t sb = smem_u32(smem);
    int tid = threadIdx.x, lane = tid & 31, wid = tid >> 5;
    int warp_m = wid * 32;
    int b = bh >> 4, h = bh & 15;
    int nch = 2 * tt + 2;

    const uint32_t* k0 = g_k + (size_t)bh * S_ * 32;
    const uint32_t* v0 = g_v + (size_t)bh * S_ * 32;

    // prologue: stage q straight from fp32 qkv (w=0 plane), fp16-convert into smem
    {
        const float* qsrc = qkv + ((size_t)(b * S_ + tt * 128) * 3) * (H_ * D_) + h * D_;
        for (int idx = tid; idx < 128 * 16; idx += 128) {
            int r = idx >> 4, c4 = idx & 15;
            float4 v = *reinterpret_cast<const float4*>(qsrc + (size_t)r * 3072 + c4 * 4);
            uint32_t off0 = sw128((uint32_t)(r * 128 + c4 * 8));
            uint32_t off1 = sw128((uint32_t)(r * 128 + c4 * 8 + 4));
            *reinterpret_cast<uint32_t*>(smem + off0) = pack_f16(v.x, v.y);
            *reinterpret_cast<uint32_t*>(smem + off1) = pack_f16(v.z, v.w);
        }
    }
    issue_panel1(k0, sb + SMK(0), tid);
    CP_COMMIT();
    issue_panel1(k0 + 2048, sb + SMK(1), tid);
    CP_COMMIT();
    __syncthreads();

    uint32_t qf[2][4][4];
#pragma unroll
    for (int mi = 0; mi < 2; mi++)
#pragma unroll
        for (int kf = 0; kf < 4; kf++)
            ldsm_x4(sb + SMQ, warp_m + mi * 16, kf * 16, lane, qf[mi][kf]);

    int t0 = tt * 128 + warp_m + (lane >> 2);
    int cp0 = (lane & 3) * 2;
    int row_hi = tt * 128 + warp_m + 31;

    // ---------------- phase 1: o2 ----------------
    float o2acc[2][8][4] = {};
    for (int ch = 0; ch < nch; ch++) {
        if (ch + 1 < nch) CP_WAIT1(); else CP_WAIT0();
        __syncthreads();
        if (ch + 2 < nch) {
            issue_panel1(k0 + (size_t)(ch + 2) * 2048, sb + SMK((ch + 2) % 3), tid);
            CP_COMMIT();
        }
        if (ch * 64 <= row_hi) {
            uint32_t kb = sb + SMK(ch % 3);
            chunk_gemm(kb, kb, qf, o2acc, lane, t0, cp0, ch * 64, ch >= 2 * tt,
                       ch * 64 + 32 > row_hi);
        }
    }

    // phase-2 prefetch before u-conversion (overlap DMA with math).
    int kb0 = nch % 3;
    issue_panel1(k0, sb + SMK(kb0), tid);
    issue_panel1(v0, sb + SMV(0), tid);
    CP_COMMIT();
    issue_panel1(k0 + 2048, sb + SMK((kb0 + 1) % 3), tid);
    issue_panel1(v0 + 2048, sb + SMV(1), tid);
    CP_COMMIT();

    // u = (2q - o2) * U_SCALE directly into A-frags (acc layout == A-frag layout)
    uint32_t uf[2][4][4];
#pragma unroll
    for (int mi = 0; mi < 2; mi++) {
        float uacc[8][4];
#pragma unroll
        for (int nf = 0; nf < 8; nf++)
#pragma unroll
            for (int half = 0; half < 2; half++) {
                int reg = ((nf & 1) << 1) | half;
                uint32_t qb = qf[mi][nf >> 1][reg];
                float q0 = __half2float(__ushort_as_half((unsigned short)(qb & 0xFFFF)));
                float q1 = __half2float(__ushort_as_half((unsigned short)(qb >> 16)));
                uacc[nf][half * 2 + 0] = (2.0f * q0 - o2acc[mi][nf][half * 2 + 0]) * U_SCALE;
                uacc[nf][half * 2 + 1] = (2.0f * q1 - o2acc[mi][nf][half * 2 + 1]) * U_SCALE;
            }
#pragma unroll
        for (int kf = 0; kf < 4; kf++) {
            uf[mi][kf][0] = pack_f16(uacc[2*kf  ][0], uacc[2*kf  ][1]);
            uf[mi][kf][1] = pack_f16(uacc[2*kf  ][2], uacc[2*kf  ][3]);
            uf[mi][kf][2] = pack_f16(uacc[2*kf+1][0], uacc[2*kf+1][1]);
            uf[mi][kf][3] = pack_f16(uacc[2*kf+1][2], uacc[2*kf+1][3]);
        }
    }

    // ---------------- phase 2: out ----------------
    float outacc[2][8][4] = {};
    for (int ch = 0; ch < nch; ch++) {
        if (ch + 1 < nch) CP_WAIT1(); else CP_WAIT0();
        __syncthreads();
        if (ch + 2 < nch) {
            issue_panel1(k0 + (size_t)(ch + 2) * 2048, sb + SMK((kb0 + ch + 2) % 3), tid);
            issue_panel1(v0 + (size_t)(ch + 2) * 2048, sb + SMV((ch + 2) % 3), tid);
            CP_COMMIT();
        }
        if (ch * 64 <= row_hi) {
            uint32_t kb = sb + SMK((kb0 + ch) % 3);
            uint32_t vb = sb + SMV(ch % 3);
            chunk_gemm(kb, vb, uf, outacc, lane, t0, cp0, ch * 64, ch >= 2 * tt,
                       ch * 64 + 32 > row_hi);
        }
    }

    // out (B,S,H,D) fp32, undo U_SCALE
#pragma unroll
    for (int mi = 0; mi < 2; mi++)
#pragma unroll
        for (int half = 0; half < 2; half++) {
            int t = t0 + mi * 16 + half * 8;
            float* op = out + (((size_t)(b * S_ + t)) * 16 + h) * 64;
#pragma unroll
            for (int nf = 0; nf < 8; nf++) {
                float2 v = make_float2(outacc[mi][nf][half * 2 + 0] * U_UNSCALE,
                                       outacc[mi][nf][half * 2 + 1] * U_UNSCALE);
                *reinterpret_cast<float2*>(op + nf * 8 + cp0) = v;
            }
        }
}

// ===========================================================================
extern "C" void kernel_launch(void* const* d_in, const int* in_sizes, int n_in,
                              void* d_out, int out_size) {
    const float* qkv = (const float*)d_in[0];
    float* out = (float*)d_out;

    static bool attr_done = false;
    if (!attr_done) {
        cudaFuncSetAttribute(fused, cudaFuncAttributeMaxDynamicSharedMemorySize, SMEM_BYTES);
        attr_done = true;
    }

    prep<<<B_ * S_ * 2 * H_ * 16 / 256, 256>>>(qkv);
    dim3 grid(16, BH_);
    fused<<<grid, 128, SMEM_BYTES>>>(qkv, out);
}